// round 15
// baseline (speedup 1.0000x reference)
#include <cuda_runtime.h>
#include <cuda_fp16.h>
#include <cstdint>
#include <cstddef>

// Problem dims
#define BB 64
#define TT 256
#define DD 512
#define HH 1024
#define G4 4096
#define NCTA_S 64       // scan CTAs (UPC=16)
#define UPC 16
// time chunking
#define NTC 8
#define TPC 32
// ---- fp16 GEMM smem (bytes) ----
#define A_ROW_B 80
#define W_ROW_B 80
#define GEMM_STAGE_B (128*A_ROW_B + 64*W_ROW_B)   // 15360
#define GEMM_SMEM_BYTES (3*GEMM_STAGE_B)          // 46080
// ---- fp16 scan smem (bytes) ----
#define KCH 128                      // halves per chunk
#define NCH 8
#define HROW_B 272                   // 128 halves + 16B pad (4-bank row shift)
#define HSLOT_B (64*HROW_B)          // 17408
#define UROW_B 2064                  // 1024 halves + pad
#define US_B (64*UROW_B)             // 132096 (64 gate-cols)
#define PLANE_FLOATS (64*33)         // 2112
#define SCAN_SMEM_BYTES (US_B + 4*HSLOT_B)   // 201728

// ---------------- scratch ----------------
__device__ float    g_xz[(size_t)TT*BB*G4];      // gate pre-acts (fp32), reused by both layers
__device__ __half   g_seq1[(size_t)BB*TT*HH];    // layer-1 output (fp16)
__device__ __half   g_xh[(size_t)BB*TT*DD];
__device__ __half   g_W1h[(size_t)G4*DD];        // W1 n-major fp16
__device__ __half   g_W2h[(size_t)G4*HH];        // W2 n-major fp16
__device__ __half   g_h1[2*BB*HH];
__device__ __half   g_h2[2*BB*HH];
__device__ float    g_c1[BB*HH];
__device__ float    g_c2[BB*HH];
__device__ unsigned g_flag[2][NCTA_S * 32];
__device__ unsigned g_epoch[2];

// ---------------- helpers ----------------
__device__ __forceinline__ void mma_f16(float c[4], const unsigned a[4], unsigned b0, unsigned b1) {
    asm volatile(
        "mma.sync.aligned.m16n8k16.row.col.f32.f16.f16.f32 "
        "{%0,%1,%2,%3}, {%4,%5,%6,%7}, {%8,%9}, {%0,%1,%2,%3};\n"
        : "+f"(c[0]), "+f"(c[1]), "+f"(c[2]), "+f"(c[3])
        : "r"(a[0]), "r"(a[1]), "r"(a[2]), "r"(a[3]), "r"(b0), "r"(b1));
}
__device__ __forceinline__ void cp16_ca(void* smem_dst, const void* gsrc) {
    unsigned d = (unsigned)__cvta_generic_to_shared(smem_dst);
    asm volatile("cp.async.ca.shared.global [%0], [%1], 16;\n" :: "r"(d), "l"(gsrc) : "memory");
}
__device__ __forceinline__ void cp16_cg(void* smem_dst, const void* gsrc) {
    unsigned d = (unsigned)__cvta_generic_to_shared(smem_dst);
    asm volatile("cp.async.cg.shared.global [%0], [%1], 16;\n" :: "r"(d), "l"(gsrc) : "memory");
}
__device__ __forceinline__ void cp_commit() { asm volatile("cp.async.commit_group;\n" ::: "memory"); }
__device__ __forceinline__ void cp_wait1() { asm volatile("cp.async.wait_group 1;\n" ::: "memory"); }
__device__ __forceinline__ void cp_wait2() { asm volatile("cp.async.wait_group 2;\n" ::: "memory"); }
__device__ __forceinline__ float sigf(float x) { return 1.f / (1.f + __expf(-x)); }

// ---------------- init ----------------
__global__ void init_zero() {
    int idx = blockIdx.x * blockDim.x + threadIdx.x;
    int stride = gridDim.x * blockDim.x;
    for (int i = idx; i < 2 * BB * HH; i += stride) {
        g_h1[i] = __float2half_rn(0.f); g_h2[i] = __float2half_rn(0.f);
    }
    for (int i = idx; i < BB * HH; i += stride) { g_c1[i] = 0.f; g_c2[i] = 0.f; }
    for (int i = idx; i < NCTA_S * 32; i += stride) { g_flag[0][i] = 0u; g_flag[1][i] = 0u; }
    if (idx == 0) { g_epoch[0] = 0u; g_epoch[1] = 0u; }
}

// ---------------- x -> fp16 ----------------
__global__ void __launch_bounds__(256)
cvt_x(const float* __restrict__ src, int n4) {
    int idx = blockIdx.x * blockDim.x + threadIdx.x;
    int stride = gridDim.x * blockDim.x;
    const float4* s4 = (const float4*)src;
    uint2* d4 = (uint2*)g_xh;
    for (int i = idx; i < n4; i += stride) {
        float4 v = s4[i];
        __half2 p0 = __floats2half2_rn(v.x, v.y);
        __half2 p1 = __floats2half2_rn(v.z, v.w);
        uint2 u;
        u.x = *(unsigned*)&p0; u.y = *(unsigned*)&p1;
        d4[i] = u;
    }
}

// ---------------- W [K][G4] fp32 -> [G4][K] fp16 (tiled transpose) ----------------
__global__ void __launch_bounds__(256)
cvt_w_t(const float* __restrict__ src, int which, int K) {
    __shared__ float tile[32][33];
    __half* dst = which ? g_W2h : g_W1h;
    int k0 = blockIdx.y * 32, n0 = blockIdx.x * 32;
    int tx = threadIdx.x & 31, ty = threadIdx.x >> 5;
#pragma unroll
    for (int i = 0; i < 32; i += 8)
        tile[ty + i][tx] = src[(size_t)(k0 + ty + i) * G4 + n0 + tx];
    __syncthreads();
#pragma unroll
    for (int i = 0; i < 32; i += 8)
        dst[(size_t)(n0 + ty + i) * K + k0 + tx] = __float2half_rn(tile[tx][ty + i]);
}

// ---------------- fp16 GEMM (time-chunked rows [m0, m0+2048)) ----------------
__global__ void __launch_bounds__(256)
gemm_xw(int asel, const float* __restrict__ bias, int K, int sAb, int sAt, int m0)
{
    extern __shared__ char smem[];
    const __half* A = asel ? g_seq1 : g_xh;
    const __half* W = asel ? g_W2h : g_W1h;

    const int tid = threadIdx.x;
    const int lane = tid & 31, w = tid >> 5;
    const int wm = w & 3, wn = w >> 2;
    const int bn = blockIdx.x * 64;
    const int bm = m0 + blockIdx.y * 128;
    const int lr = lane >> 2, lc = lane & 3;

    float cf[2][4][4];
#pragma unroll
    for (int i = 0; i < 2; i++)
#pragma unroll
        for (int j = 0; j < 4; j++)
#pragma unroll
            for (int q = 0; q < 4; q++) cf[i][j][q] = 0.f;

    const int KB = K >> 5;

    auto dostage = [&](int slot, int kb) {
        char* As = smem + slot * GEMM_STAGE_B;
        char* Ws = As + 128 * A_ROW_B;
        const int k0 = kb * 32;
#pragma unroll
        for (int i = 0; i < 2; i++) {
            int idx = i * 256 + tid;
            int r = idx >> 2, s = idx & 3;
            int m = bm + r;
            const __half* src = A + (size_t)(m & 63) * sAb + (size_t)(m >> 6) * sAt + k0 + s * 8;
            cp16_ca(As + r * A_ROW_B + s * 16, src);
        }
        {
            int r = tid >> 2, s = tid & 3;
            const __half* src = W + (size_t)(bn + r) * K + k0 + s * 8;
            cp16_ca(Ws + r * W_ROW_B + s * 16, src);
        }
    };

    dostage(0, 0); cp_commit();
    dostage(1, 1); cp_commit();

    for (int kb = 0; kb < KB; kb++) {
        cp_wait1();
        __syncthreads();
        if (kb + 2 < KB) dostage((kb + 2) % 3, kb + 2);
        cp_commit();
        const char* as = smem + (kb % 3) * GEMM_STAGE_B;
        const char* ws = as + 128 * A_ROW_B;
#pragma unroll
        for (int k16 = 0; k16 < 2; k16++) {
            int kB = k16 * 32;
            unsigned a[2][4];
#pragma unroll
            for (int mt = 0; mt < 2; mt++) {
                int r0 = wm * 32 + mt * 16 + lr;
                a[mt][0] = *(const unsigned*)(as + r0 * A_ROW_B + kB + lc * 4);
                a[mt][1] = *(const unsigned*)(as + (r0 + 8) * A_ROW_B + kB + lc * 4);
                a[mt][2] = *(const unsigned*)(as + r0 * A_ROW_B + kB + 16 + lc * 4);
                a[mt][3] = *(const unsigned*)(as + (r0 + 8) * A_ROW_B + kB + 16 + lc * 4);
            }
#pragma unroll
            for (int n8 = 0; n8 < 4; n8++) {
                int c0 = wn * 32 + n8 * 8 + lr;
                unsigned b0 = *(const unsigned*)(ws + c0 * W_ROW_B + kB + lc * 4);
                unsigned b1 = *(const unsigned*)(ws + c0 * W_ROW_B + kB + 16 + lc * 4);
#pragma unroll
                for (int mt = 0; mt < 2; mt++) mma_f16(cf[mt][n8], a[mt], b0, b1);
            }
        }
    }

#pragma unroll
    for (int mt = 0; mt < 2; mt++) {
#pragma unroll
        for (int nt = 0; nt < 4; nt++) {
            int gr = bm + wm * 32 + mt * 16 + lr;
            int gc = bn + wn * 32 + nt * 8 + 2 * lc;
            float bv0 = bias[gc], bv1 = bias[gc + 1];
            float2 v;
            v.x = cf[mt][nt][0] + bv0; v.y = cf[mt][nt][1] + bv1;
            *(float2*)&g_xz[(size_t)gr * G4 + gc] = v;
            v.x = cf[mt][nt][2] + bv0; v.y = cf[mt][nt][3] + bv1;
            *(float2*)&g_xz[(size_t)(gr + 8) * G4 + gc] = v;
        }
    }
}

// ---------------- fp16 scan: 64 CTAs, UPC=16, split k x4 / n x2 ----------------
__device__ __forceinline__ void lstm_load_chunk(const __half* hr, int ch, char* slot, int tid) {
#pragma unroll
    for (int i = 0; i < 4; i++) {    // 64 rows x 16 segs(16B)
        int idx = i * 256 + tid;
        int r = idx >> 4, s = idx & 15;
        cp16_cg(slot + r * HROW_B + s * 16, hr + (size_t)r * HH + ch * KCH + s * 8);
    }
}

__global__ void __launch_bounds__(256)
lstm_scan(const float* __restrict__ U, int layer, int t0)
{
    extern __shared__ char smem[];
    char* UsB = smem;                 // [64 cols][1024 halves + pad]
    char* Hst = smem + US_B;          // 4 slots of [64][128 halves + pad]
    float* PL = (float*)Hst;          // 8-plane overlay (67584B <= 69632B)

    __half* hbuf = (layer == 0) ? g_h1 : g_h2;
    float* cbuf = (layer == 0) ? g_c1 : g_c2;
    __half* seqo = (layer == 0) ? g_seq1 : nullptr;
    volatile unsigned* flags = g_flag[layer];
    volatile unsigned* epoch = &g_epoch[layer];

    const int tid = threadIdx.x, lane = tid & 31, wid = tid >> 5;
    const int u0 = blockIdx.x * UPC;
    const int lr = lane >> 2, lc = lane & 3;
    const int kq = wid & 3, nh = wid >> 2;
    const int klB = kq * 64;          // this warp's 32-halves k-slice (bytes) within 256B chunk row

    // U slice: 64 cols (gate*16+u), k-major fp16
    for (int idx = tid; idx < 64 * HH; idx += 256) {
        int k = idx >> 6, c = idx & 63;
        int gcol = (c >> 4) * HH + u0 + (c & 15);
        ((__half*)UsB)[c * (UROW_B / 2) + k] = __float2half_rn(U[(size_t)k * G4 + gcol]);
    }
    __syncthreads();

    const int uu = tid & 15;
    const int bb0 = tid >> 4;         // items: (bb0 + 16j, uu), j = 0..3
    float cc[4];
#pragma unroll
    for (int j = 0; j < 4; j++) cc[j] = cbuf[(size_t)(bb0 + 16 * j) * HH + u0 + uu];

    float cf[4][4][4];
#pragma unroll
    for (int mt = 0; mt < 4; mt++)
#pragma unroll
        for (int n8 = 0; n8 < 4; n8++)
#pragma unroll
            for (int q = 0; q < 4; q++) cf[mt][n8][q] = 0.f;

    for (int t = t0; t < t0 + TPC; t++) {
        const __half* hr = hbuf + (t & 1) * (BB * HH);
        __half* hw = hbuf + ((t + 1) & 1) * (BB * HH);

        // prefetch xz gate rows: 4 items x 4 gates
        float xr[4][4];
        {
            const float* xz = g_xz + (size_t)(t * BB) * G4;
#pragma unroll
            for (int j = 0; j < 4; j++) {
                const float* xp = xz + (size_t)(bb0 + 16 * j) * G4 + u0 + uu;
#pragma unroll
                for (int g = 0; g < 4; g++) xr[j][g] = __ldg(xp + g * HH);
            }
        }

        lstm_load_chunk(hr, 0, Hst + 0 * HSLOT_B, tid); cp_commit();
        lstm_load_chunk(hr, 1, Hst + 1 * HSLOT_B, tid); cp_commit();
        lstm_load_chunk(hr, 2, Hst + 2 * HSLOT_B, tid); cp_commit();

        for (int ch = 0; ch < NCH; ch++) {
            cp_wait2();
            __syncthreads();
            if (ch + 3 < NCH) lstm_load_chunk(hr, ch + 3, Hst + ((ch + 3) & 3) * HSLOT_B, tid);
            cp_commit();
            const char* hs = Hst + (ch & 3) * HSLOT_B;
            const int chB = ch * 256;
#pragma unroll
            for (int k16 = 0; k16 < 2; k16++) {
                const int kB = klB + k16 * 32;
                unsigned a[4][4];
#pragma unroll
                for (int mt = 0; mt < 4; mt++) {
                    int r0 = mt * 16 + lr;
                    a[mt][0] = *(const unsigned*)(hs + r0 * HROW_B + kB + lc * 4);
                    a[mt][1] = *(const unsigned*)(hs + (r0 + 8) * HROW_B + kB + lc * 4);
                    a[mt][2] = *(const unsigned*)(hs + r0 * HROW_B + kB + 16 + lc * 4);
                    a[mt][3] = *(const unsigned*)(hs + (r0 + 8) * HROW_B + kB + 16 + lc * 4);
                }
#pragma unroll
                for (int n8 = 0; n8 < 4; n8++) {
                    int c0 = nh * 32 + n8 * 8 + lr;
                    unsigned b0 = *(const unsigned*)(UsB + c0 * UROW_B + chB + kB + lc * 4);
                    unsigned b1 = *(const unsigned*)(UsB + c0 * UROW_B + chB + kB + 16 + lc * 4);
#pragma unroll
                    for (int mt = 0; mt < 4; mt++) mma_f16(cf[mt][n8], a[mt], b0, b1);
                }
            }
        }

        __syncthreads();   // all warps done with slots -> plane overlay

        {
            float* pl = PL + wid * PLANE_FLOATS;   // planes 0-3: cols 0-31; planes 4-7: cols 32-63
#pragma unroll
            for (int mt = 0; mt < 4; mt++)
#pragma unroll
                for (int n8 = 0; n8 < 4; n8++) {
                    int zr = mt * 16 + lr, zc = n8 * 8 + 2 * lc;
                    pl[zr * 33 + zc]           = cf[mt][n8][0];
                    pl[zr * 33 + zc + 1]       = cf[mt][n8][1];
                    pl[(zr + 8) * 33 + zc]     = cf[mt][n8][2];
                    pl[(zr + 8) * 33 + zc + 1] = cf[mt][n8][3];
                    cf[mt][n8][0] = 0.f; cf[mt][n8][1] = 0.f;
                    cf[mt][n8][2] = 0.f; cf[mt][n8][3] = 0.f;
                }
        }
        __syncthreads();

        // reduce 4 planes per half + gate math; cols: gate g -> local col (g&1)*16 + uu, half g>>1
#pragma unroll
        for (int j = 0; j < 4; j++) {
            int b = bb0 + 16 * j;
            float zi = xr[j][0], zf = xr[j][1], zg = xr[j][2], zo = xr[j][3];
#pragma unroll
            for (int p = 0; p < 4; p++) {
                const float* pa = PL + p * PLANE_FLOATS + b * 33;        // half 0: gates 0,1
                const float* pb = PL + (p + 4) * PLANE_FLOATS + b * 33;  // half 1: gates 2,3
                zi += pa[uu]; zf += pa[16 + uu];
                zg += pb[uu]; zo += pb[16 + uu];
            }
            float fi = sigf(zi), ff = sigf(zf), fo = sigf(zo);
            float fg = tanhf(zg);
            float cn = ff * cc[j] + fi * fg;
            cc[j] = cn;
            __half hnr = __float2half_rn(fo * tanhf(cn));
            hw[(size_t)b * HH + u0 + uu] = hnr;
            if (seqo) seqo[((size_t)b * TT + t) * HH + u0 + uu] = hnr;
        }

        // grid barrier (64 CTAs): per-CTA arrive slots + single release epoch
        __threadfence();
        __syncthreads();
        if (tid == 0) flags[blockIdx.x * 32] = (unsigned)(t + 1);
        if (blockIdx.x == 0) {
            if (tid < NCTA_S) {
                while (flags[tid * 32] < (unsigned)(t + 1)) { }
            }
            __syncthreads();
            if (tid == 0) *epoch = (unsigned)(t + 1);
        }
        if (tid == 0) {
            while (*epoch < (unsigned)(t + 1)) { __nanosleep(32); }
        }
        __syncthreads();
        __threadfence();
    }

#pragma unroll
    for (int j = 0; j < 4; j++)
        cbuf[(size_t)(bb0 + 16 * j) * HH + u0 + uu] = cc[j];
}

// ---------------- final dense ----------------
__global__ void __launch_bounds__(512)
dense_out(const float* __restrict__ Wd, const float* __restrict__ bd, float* __restrict__ out)
{
    __shared__ float hs[HH];
    int b = blockIdx.x;
    const __half* h = g_h2;   // h_256 in stage 0 (T even)
    for (int i = threadIdx.x; i < HH; i += 512) hs[i] = __half2float(h[(size_t)b * HH + i]);
    __syncthreads();
    int o = threadIdx.x;
    float acc = bd[o];
#pragma unroll 8
    for (int k = 0; k < HH; k++) acc += hs[k] * Wd[(size_t)k * 512 + o];
    out[(size_t)b * 512 + o] = acc;
}

// ---------------- launch: serial-alternating scans + event-gated gemm overlay ----------------
extern "C" void kernel_launch(void* const* d_in, const int* in_sizes, int n_in,
                              void* d_out, int out_size)
{
    (void)in_sizes; (void)n_in; (void)out_size;
    const float* x  = (const float*)d_in[0];
    const float* W1 = (const float*)d_in[1];
    const float* U1 = (const float*)d_in[2];
    const float* b1 = (const float*)d_in[3];
    const float* W2 = (const float*)d_in[4];
    const float* U2 = (const float*)d_in[5];
    const float* b2 = (const float*)d_in[6];
    const float* Wd = (const float*)d_in[7];
    const float* bd = (const float*)d_in[8];
    float* out = (float*)d_out;

    static cudaStream_t s1 = nullptr;
    static cudaEvent_t evF, evG1[NTC], evL1[NTC], evG2[NTC], evJ1;
    if (!s1) {
        cudaStreamCreateWithFlags(&s1, cudaStreamNonBlocking);
        cudaEventCreateWithFlags(&evF, cudaEventDisableTiming);
        cudaEventCreateWithFlags(&evJ1, cudaEventDisableTiming);
        for (int k = 0; k < NTC; k++) {
            cudaEventCreateWithFlags(&evG1[k], cudaEventDisableTiming);
            cudaEventCreateWithFlags(&evL1[k], cudaEventDisableTiming);
            cudaEventCreateWithFlags(&evG2[k], cudaEventDisableTiming);
        }
        cudaFuncSetAttribute(gemm_xw,   cudaFuncAttributeMaxDynamicSharedMemorySize, GEMM_SMEM_BYTES);
        cudaFuncSetAttribute(lstm_scan, cudaFuncAttributeMaxDynamicSharedMemorySize, SCAN_SMEM_BYTES);
    }

    // prologue on the capturing stream
    init_zero<<<128, 256>>>();
    cvt_x<<<1024, 256>>>(x, (BB * TT * DD) / 4);
    {
        dim3 gt1(G4 / 32, DD / 32);
        cvt_w_t<<<gt1, 256>>>(W1, 0, DD);
        dim3 gt2(G4 / 32, HH / 32);
        cvt_w_t<<<gt2, 256>>>(W2, 1, HH);
    }

    // fork gemm stream
    cudaEventRecord(evF, 0);
    cudaStreamWaitEvent(s1, evF, 0);

    dim3 ggc(G4 / 64, (TPC * 64) / 128);

    // gemm1 chunks on s1 (first runs at full chip; later ones hide under scan chunks)
    for (int k = 0; k < NTC; k++) {
        gemm_xw<<<ggc, 256, GEMM_SMEM_BYTES, s1>>>(0, b1, DD, TT * DD, DD, k * TPC * 64);
        cudaEventRecord(evG1[k], s1);
    }

    // serial-alternating scans on stream 0; gemm2 chunks hide under the NEXT lstm1 chunk
    for (int k = 0; k < NTC; k++) {
        cudaStreamWaitEvent(0, evG1[k], 0);
        lstm_scan<<<NCTA_S, 256, SCAN_SMEM_BYTES>>>(U1, 0, k * TPC);
        cudaEventRecord(evL1[k], 0);

        cudaStreamWaitEvent(s1, evL1[k], 0);
        gemm_xw<<<ggc, 256, GEMM_SMEM_BYTES, s1>>>(1, b2, HH, TT * HH, HH, k * TPC * 64);
        cudaEventRecord(evG2[k], s1);

        if (k >= 1) {
            cudaStreamWaitEvent(0, evG2[k - 1], 0);
            lstm_scan<<<NCTA_S, 256, SCAN_SMEM_BYTES>>>(U2, 1, (k - 1) * TPC);
        }
    }
    cudaStreamWaitEvent(0, evG2[NTC - 1], 0);
    lstm_scan<<<NCTA_S, 256, SCAN_SMEM_BYTES>>>(U2, 1, (NTC - 1) * TPC);

    dense_out<<<BB, 512>>>(Wd, bd, out);

    cudaEventRecord(evJ1, s1);
    cudaStreamWaitEvent(0, evJ1, 0);
}